// round 4
// baseline (speedup 1.0000x reference)
#include <cuda_runtime.h>
#include <cuda_bf16.h>
#include <cuda_fp16.h>
#include <cstdint>

// Problem constants
#define NROWS   12288
#define DK      128
#define MTILES  96           // NROWS / 128
#define SPLITS  6            // J-dimension splits
#define JCHUNK  16           // J-tiles per item (96/6)
#define ITEMS   (MTILES * SPLITS)   // 576
#define GRID    148
#define NTHREADS 256

// fp8 tiles: 128 rows x 128 bytes = 16KB
#define ROWB     128
#define TILEB    (128 * ROWB)

// SMEM layout (dynamic): A tile 16KB, B double buffer 2x16KB, rowsum 512B
#define SM_A     0
#define SM_B0    16384
#define SM_B1    32768
#define SM_ROW   49152
#define SM_TOTAL (SM_ROW + 512)

// exp(sim/T) = 2^(dot * log2(e)/T)
static constexpr float EXP_SCALE = 1.4426950408889634f / 0.07f;

// Scratch (allocation-free): e4m3 copy of x, per-row self-dot of quantized x,
// per-split row partials.
__device__ uint8_t g_xq[NROWS * DK];
__device__ float   g_selfdot[NROWS];
__device__ float   g_partial[SPLITS * NROWS];

// ---------------- PTX helpers (base sm_103 target only!) ----------------
__device__ __forceinline__ uint32_t smem_u32(const void* p) {
    uint32_t a;
    asm("{ .reg .u64 t; cvta.to.shared.u64 t, %1; cvt.u32.u64 %0, t; }" : "=r"(a) : "l"(p));
    return a;
}

__device__ __forceinline__ void cp16(uint32_t dst, const void* src) {
    asm volatile("cp.async.cg.shared.global [%0], [%1], 16;" :: "r"(dst), "l"(src));
}
#define CP_COMMIT() asm volatile("cp.async.commit_group;" ::: "memory")
#define CP_WAIT1()  asm volatile("cp.async.wait_group 1;" ::: "memory")
#define CP_WAIT0()  asm volatile("cp.async.wait_group 0;" ::: "memory")

__device__ __forceinline__ void ldm4(uint32_t addr, uint32_t* r) {
    asm volatile("ldmatrix.sync.aligned.m8n8.x4.shared.b16 {%0,%1,%2,%3}, [%4];"
        : "=r"(r[0]), "=r"(r[1]), "=r"(r[2]), "=r"(r[3]) : "r"(addr));
}

// fp8 e4m3 MMA: m16n8k32, fp32 accumulate
__device__ __forceinline__ void mma_fp8(float* c, const uint32_t* a, const uint32_t* b) {
    asm volatile(
        "mma.sync.aligned.m16n8k32.row.col.f32.e4m3.e4m3.f32 "
        "{%0,%1,%2,%3}, {%4,%5,%6,%7}, {%8,%9}, {%0,%1,%2,%3};"
        : "+f"(c[0]), "+f"(c[1]), "+f"(c[2]), "+f"(c[3])
        : "r"(a[0]), "r"(a[1]), "r"(a[2]), "r"(a[3]), "r"(b[0]), "r"(b[1]));
}

__device__ __forceinline__ float fast_exp2(float x) {
    float r;
    asm("ex2.approx.f32 %0, %1;" : "=f"(r) : "f"(x));
    return r;
}

// ---------------- kernels ----------------

// One warp per row: quantize fp32 -> e4m3, store packed, and compute the
// per-row self-dot of the QUANTIZED values (for exact diagonal replacement).
__global__ void convert_kernel(const float* __restrict__ x, float* __restrict__ out) {
    int gtid = blockIdx.x * blockDim.x + threadIdx.x;
    int row  = gtid >> 5;
    int lane = gtid & 31;

    float4 v = reinterpret_cast<const float4*>(x)[row * 32 + lane];

    uint16_t a0, a1;   // e4m3x2: low byte = second source
    asm("cvt.rn.satfinite.e4m3x2.f32 %0, %1, %2;" : "=h"(a0) : "f"(v.y), "f"(v.x));
    asm("cvt.rn.satfinite.e4m3x2.f32 %0, %1, %2;" : "=h"(a1) : "f"(v.w), "f"(v.z));
    uint32_t packed = (uint32_t)a0 | ((uint32_t)a1 << 16);
    reinterpret_cast<uint32_t*>(g_xq)[row * 32 + lane] = packed;

    // Dequantize back (exact) for the self-dot
    uint32_t h01, h23;
    asm("cvt.rn.f16x2.e4m3x2 %0, %1;" : "=r"(h01) : "h"(a0));
    asm("cvt.rn.f16x2.e4m3x2 %0, %1;" : "=r"(h23) : "h"(a1));
    __half2 q01 = *reinterpret_cast<__half2*>(&h01);
    __half2 q23 = *reinterpret_cast<__half2*>(&h23);
    float f0 = __half2float(q01.x), f1 = __half2float(q01.y);
    float f2 = __half2float(q23.x), f3 = __half2float(q23.y);
    float s = f0 * f0 + f1 * f1 + f2 * f2 + f3 * f3;
    #pragma unroll
    for (int o = 16; o > 0; o >>= 1) s += __shfl_xor_sync(0xffffffffu, s, o);
    if (lane == 0) g_selfdot[row] = s;
    if (gtid == 0) out[0] = 0.0f;
}

// Load one 128x128 e4m3 tile (row-major 128B rows) into SMEM, XOR-16B swizzle.
__device__ __forceinline__ void issue_tile_load(uint32_t sdst, const uint8_t* gsrc,
                                                int tid) {
    #pragma unroll
    for (int t = 0; t < 4; t++) {
        int q     = tid + t * NTHREADS;    // 0..1023
        int row   = q >> 3;
        int chunk = q & 7;
        cp16(sdst + row * ROWB + ((chunk ^ (row & 7)) << 4),
             gsrc + row * ROWB + chunk * 16);
    }
}

// Epilogue chunk kb (0..3): exp+accumulate the 16 values of row-group mt=kb.
__device__ __forceinline__ void epi_chunk(const float (&acc)[4][4][4], int kb,
                                          float (&rowpart)[8]) {
    const int mt = kb;
    #pragma unroll
    for (int nt = 0; nt < 4; nt++) {
        rowpart[mt * 2 + 0] += fast_exp2(acc[mt][nt][0] * EXP_SCALE);
        rowpart[mt * 2 + 0] += fast_exp2(acc[mt][nt][1] * EXP_SCALE);
        rowpart[mt * 2 + 1] += fast_exp2(acc[mt][nt][2] * EXP_SCALE);
        rowpart[mt * 2 + 1] += fast_exp2(acc[mt][nt][3] * EXP_SCALE);
    }
}

// One 128x128 tile of fp8 MMAs into `acc` (4 k-steps of k=32), with the
// epilogue of `prev` interleaved chunk-by-chunk under the k-loop.
template <bool DO_EPI>
__device__ __forceinline__ void tile_step(uint32_t sA, uint32_t bufb,
                                          float (&acc)[4][4][4],
                                          const float (&prev)[4][4][4],
                                          float (&rowpart)[8],
                                          int wm, int wn, int rsel, int csel) {
    #pragma unroll
    for (int mt = 0; mt < 4; mt++)
        #pragma unroll
        for (int nt = 0; nt < 4; nt++)
            #pragma unroll
            for (int ci = 0; ci < 4; ci++) acc[mt][nt][ci] = 0.0f;

    #pragma unroll
    for (int kb = 0; kb < 4; kb++) {
        uint32_t a[4][4];
        #pragma unroll
        for (int mt = 0; mt < 4; mt++) {
            int row = wm * 64 + mt * 16 + rsel;
            uint32_t ad = sA + row * ROWB + (((kb * 2 + csel) ^ (row & 7)) << 4);
            ldm4(ad, a[mt]);
        }
        uint32_t bf[4][2];
        #pragma unroll
        for (int np = 0; np < 2; np++) {
            int row = wn * 32 + np * 16 + rsel;
            uint32_t ad = bufb + row * ROWB + (((kb * 2 + csel) ^ (row & 7)) << 4);
            uint32_t t4[4];
            ldm4(ad, t4);
            bf[np * 2 + 0][0] = t4[0]; bf[np * 2 + 0][1] = t4[2];
            bf[np * 2 + 1][0] = t4[1]; bf[np * 2 + 1][1] = t4[3];
        }
        #pragma unroll
        for (int mt = 0; mt < 4; mt++)
            #pragma unroll
            for (int nt = 0; nt < 4; nt++)
                mma_fp8(acc[mt][nt], a[mt], bf[nt]);

        if (DO_EPI) epi_chunk(prev, kb, rowpart);
    }
}

__global__ void __launch_bounds__(NTHREADS, 1)
uniform_loss_main() {
    extern __shared__ char smem[];
    uint32_t sb = smem_u32(smem);
    float* rowsum = (float*)(smem + SM_ROW);

    const int tid  = threadIdx.x;
    const int lane = tid & 31;
    const int w    = tid >> 5;      // 0..7
    const int wm   = w & 1;         // 2 M-groups of 64 rows
    const int wn   = w >> 1;        // 4 N-groups of 32 cols
    const int rsel = lane & 15;
    const int csel = lane >> 4;
    const int g    = lane >> 2;

    const uint32_t sA = sb + SM_A;
    const uint32_t sB0 = sb + SM_B0;
    const uint32_t sB1 = sb + SM_B1;

    for (int it = blockIdx.x; it < ITEMS; it += gridDim.x) {
        const int m  = it % MTILES;
        const int s  = it / MTILES;
        const int j0 = s * JCHUNK;

        if (tid < 128) rowsum[tid] = 0.0f;

        // Prologue: A tile + B(j0) as group0; B(j0+1) as group1
        issue_tile_load(sA,  g_xq + (size_t)m * TILEB, tid);
        issue_tile_load(sB0, g_xq + (size_t)j0 * TILEB, tid);
        CP_COMMIT();
        issue_tile_load(sB1, g_xq + (size_t)(j0 + 1) * TILEB, tid);
        CP_COMMIT();

        float rowpart[8];
        #pragma unroll
        for (int r = 0; r < 8; r++) rowpart[r] = 0.0f;

        float accA[4][4][4];
        float accB[4][4][4];

        #pragma unroll 1
        for (int jjp = 0; jjp < JCHUNK; jjp += 2) {
            // ---- tile jjp (even, buffer sB0): mma->accA, epilogue of accB ----
            CP_WAIT1();
            __syncthreads();
            if (jjp == 0)
                tile_step<false>(sA, sB0, accA, accB, rowpart, wm, wn, rsel, csel);
            else
                tile_step<true >(sA, sB0, accA, accB, rowpart, wm, wn, rsel, csel);
            __syncthreads();
            if (jjp + 2 < JCHUNK) {
                issue_tile_load(sB0, g_xq + (size_t)(j0 + jjp + 2) * TILEB, tid);
                CP_COMMIT();
            }

            // ---- tile jjp+1 (odd, buffer sB1): mma->accB, epilogue of accA ----
            if (jjp + 1 == JCHUNK - 1) { CP_WAIT0(); } else { CP_WAIT1(); }
            __syncthreads();
            tile_step<true>(sA, sB1, accB, accA, rowpart, wm, wn, rsel, csel);
            __syncthreads();
            if (jjp + 3 < JCHUNK) {
                issue_tile_load(sB1, g_xq + (size_t)(j0 + jjp + 3) * TILEB, tid);
                CP_COMMIT();
            }
        }

        // Final epilogue: last tile (odd -> accB)
        #pragma unroll
        for (int kb = 0; kb < 4; kb++) epi_chunk(accB, kb, rowpart);

        // Reduce row partials: quad shuffle (lanes sharing a row), then SMEM atomics
        #pragma unroll
        for (int r = 0; r < 8; r++) {
            float v = rowpart[r];
            v += __shfl_xor_sync(0xffffffffu, v, 1);
            v += __shfl_xor_sync(0xffffffffu, v, 2);
            if ((lane & 3) == 0) {
                int row = wm * 64 + (r >> 1) * 16 + (r & 1) * 8 + g;
                atomicAdd(&rowsum[row], v);
            }
        }
        __syncthreads();
        if (tid < 128)
            g_partial[(size_t)s * NROWS + m * 128 + tid] = rowsum[tid];
        __syncthreads();
    }
}

__global__ void finalize_kernel(float* __restrict__ out) {
    int i = blockIdx.x * blockDim.x + threadIdx.x;   // 0..NROWS-1
    float v = 0.0f;
    #pragma unroll
    for (int s = 0; s < SPLITS; s++) v += g_partial[(size_t)s * NROWS + i];
    // Exact diagonal replacement: remove fp8 diag term, add reference diag
    // (sim_ii = 1.0 for L2-normalized rows).
    v += fast_exp2(EXP_SCALE) - fast_exp2(EXP_SCALE * g_selfdot[i]);
    float L = __logf(v);

    #pragma unroll
    for (int o = 16; o > 0; o >>= 1) L += __shfl_xor_sync(0xffffffffu, L, o);

    __shared__ float ws[8];
    int lane = threadIdx.x & 31, wid = threadIdx.x >> 5;
    if (lane == 0) ws[wid] = L;
    __syncthreads();
    if (threadIdx.x == 0) {
        float t = 0.0f;
        #pragma unroll
        for (int k = 0; k < 8; k++) t += ws[k];
        atomicAdd(out, t * (1.0f / (float)NROWS));
    }
}

// ---------------- host launch ----------------

extern "C" void kernel_launch(void* const* d_in, const int* in_sizes, int n_in,
                              void* d_out, int out_size) {
    const float* x = (const float*)d_in[0];
    float* out = (float*)d_out;

    // warp per row: 12288 warps = 1536 blocks of 256
    convert_kernel<<<NROWS / 8, 256>>>(x, out);

    cudaFuncSetAttribute(uniform_loss_main,
                         cudaFuncAttributeMaxDynamicSharedMemorySize, SM_TOTAL);
    uniform_loss_main<<<GRID, NTHREADS, SM_TOTAL>>>();

    finalize_kernel<<<NROWS / 256, 256>>>(out);
}

// round 6
// speedup vs baseline: 1.3011x; 1.3011x over previous
#include <cuda_runtime.h>
#include <cuda_bf16.h>
#include <cstdint>

// Problem constants
#define NROWS   12288
#define DK      128
#define MTILES  96           // NROWS / 128
#define JC      8            // j-tiles per work item (chunk)
#define ITEMS   624          // sum_i ceil((96-i)/8)
#define GRID    148
#define NTHREADS 256

// SMEM layout (dynamic): A tile 32KB, B double buffer 2x32KB, rowsum 512B
#define SM_A     0
#define SM_B0    32768
#define SM_B1    65536
#define SM_ROW   98304
#define SM_TOTAL (SM_ROW + 512)

// exp(sim/T) = 2^(dot * log2(e)/T)
static constexpr float EXP_SCALE = 1.4426950408889634f / 0.07f;

// Scratch (allocation-free): bf16 copy of x + global per-row exp-sums
__device__ __nv_bfloat16 g_xbf[NROWS * DK];
__device__ float g_rowsum[NROWS];

// ---------------- PTX helpers (base sm_103 target only) ----------------
__device__ __forceinline__ uint32_t smem_u32(const void* p) {
    uint32_t a;
    asm("{ .reg .u64 t; cvta.to.shared.u64 t, %1; cvt.u32.u64 %0, t; }" : "=r"(a) : "l"(p));
    return a;
}

__device__ __forceinline__ void cp16(uint32_t dst, const void* src) {
    asm volatile("cp.async.cg.shared.global [%0], [%1], 16;" :: "r"(dst), "l"(src));
}
#define CP_COMMIT() asm volatile("cp.async.commit_group;" ::: "memory")
#define CP_WAIT1()  asm volatile("cp.async.wait_group 1;" ::: "memory")
#define CP_WAIT0()  asm volatile("cp.async.wait_group 0;" ::: "memory")

__device__ __forceinline__ void ldm4(uint32_t addr, uint32_t* r) {
    asm volatile("ldmatrix.sync.aligned.m8n8.x4.shared.b16 {%0,%1,%2,%3}, [%4];"
        : "=r"(r[0]), "=r"(r[1]), "=r"(r[2]), "=r"(r[3]) : "r"(addr));
}

__device__ __forceinline__ void mma16816(float* c, const uint32_t* a, const uint32_t* b) {
    asm volatile(
        "mma.sync.aligned.m16n8k16.row.col.f32.bf16.bf16.f32 "
        "{%0,%1,%2,%3}, {%4,%5,%6,%7}, {%8,%9}, {%0,%1,%2,%3};"
        : "+f"(c[0]), "+f"(c[1]), "+f"(c[2]), "+f"(c[3])
        : "r"(a[0]), "r"(a[1]), "r"(a[2]), "r"(a[3]), "r"(b[0]), "r"(b[1]));
}

__device__ __forceinline__ float fast_exp2(float x) {
    float r;
    asm("ex2.approx.f32 %0, %1;" : "=f"(r) : "f"(x));
    return r;
}

// ---------------- kernels ----------------

__global__ void convert_kernel(const float* __restrict__ x, float* __restrict__ out) {
    int i = blockIdx.x * blockDim.x + threadIdx.x;
    if (i < NROWS * DK / 4) {
        float4 v = reinterpret_cast<const float4*>(x)[i];
        __nv_bfloat162* dst = reinterpret_cast<__nv_bfloat162*>(g_xbf);
        dst[2 * i]     = __floats2bfloat162_rn(v.x, v.y);
        dst[2 * i + 1] = __floats2bfloat162_rn(v.z, v.w);
    }
    if (i < NROWS) g_rowsum[i] = 0.0f;   // must reset every launch (graph replay)
    if (i == 0) out[0] = 0.0f;
}

// Load one 128x128 bf16 tile (row-major 256B rows) into SMEM with XOR-16B swizzle.
__device__ __forceinline__ void issue_tile_load(uint32_t sdst, const __nv_bfloat16* gsrc,
                                                int tid) {
    const char* base = (const char*)gsrc;
    #pragma unroll
    for (int t = 0; t < 8; t++) {
        int q   = tid + t * NTHREADS;      // 0..2047
        int row = q >> 4;
        int col = q & 15;
        cp16(sdst + row * 256 + ((col ^ (row & 7)) << 4),
             base + row * 256 + col * 16);
    }
}

// Epilogue chunk kb (0..7): exp + row-partial (+ col-partial for off-diag tiles).
// m16n8k16 acc layout: c0,c1 -> row lane/4, cols 2(lane&3),2(lane&3)+1;
//                      c2,c3 -> row lane/4+8, same cols.
template <bool COL>
__device__ __forceinline__ void epi_chunk(const float (&acc)[4][4][4], int kb,
                                          float (&rowpart)[8], float (&colpart)[8]) {
    const int mt  = kb >> 1;
    const int ntb = (kb & 1) * 2;
    #pragma unroll
    for (int nt = ntb; nt < ntb + 2; nt++) {
        float e0 = fast_exp2(acc[mt][nt][0] * EXP_SCALE);
        float e1 = fast_exp2(acc[mt][nt][1] * EXP_SCALE);
        float e2 = fast_exp2(acc[mt][nt][2] * EXP_SCALE);
        float e3 = fast_exp2(acc[mt][nt][3] * EXP_SCALE);
        rowpart[mt * 2 + 0] += e0 + e1;
        rowpart[mt * 2 + 1] += e2 + e3;
        if (COL) {
            colpart[nt * 2 + 0] += e0 + e2;
            colpart[nt * 2 + 1] += e1 + e3;
        }
    }
}

// Flush column partials of one completed off-diag tile to g_rowsum[jglob rows].
__device__ __forceinline__ void col_flush(float (&colpart)[8], int jglob,
                                          int wn, int lane) {
    #pragma unroll
    for (int q = 0; q < 8; q++) {
        float v = colpart[q];
        v += __shfl_xor_sync(0xffffffffu, v, 4);
        v += __shfl_xor_sync(0xffffffffu, v, 8);
        v += __shfl_xor_sync(0xffffffffu, v, 16);
        if (lane < 4) {
            int col = jglob * 128 + wn * 32 + (q >> 1) * 8 + lane * 2 + (q & 1);
            atomicAdd(&g_rowsum[col], v);
        }
        colpart[q] = 0.0f;
    }
}

// One 128x128 tile of MMAs into `acc`, with the epilogue of `prev` interleaved
// chunk-by-chunk under the k-loop so MUFU/FMA overlap the tensor pipe.
template <bool DO_EPI, bool COL>
__device__ __forceinline__ void tile_step(uint32_t sA, uint32_t bufb,
                                          float (&acc)[4][4][4],
                                          const float (&prev)[4][4][4],
                                          float (&rowpart)[8], float (&colpart)[8],
                                          int wm, int wn, int rsel, int csel) {
    #pragma unroll
    for (int mt = 0; mt < 4; mt++)
        #pragma unroll
        for (int nt = 0; nt < 4; nt++)
            #pragma unroll
            for (int ci = 0; ci < 4; ci++) acc[mt][nt][ci] = 0.0f;

    #pragma unroll
    for (int kb = 0; kb < 8; kb++) {
        uint32_t a[4][4];
        #pragma unroll
        for (int mt = 0; mt < 4; mt++) {
            int row = wm * 64 + mt * 16 + rsel;
            uint32_t ad = sA + row * 256 + (((kb * 2 + csel) ^ (row & 7)) << 4);
            ldm4(ad, a[mt]);
        }
        uint32_t bf[4][2];
        #pragma unroll
        for (int np = 0; np < 2; np++) {
            int row = wn * 32 + np * 16 + rsel;
            uint32_t ad = bufb + row * 256 + (((kb * 2 + csel) ^ (row & 7)) << 4);
            uint32_t t4[4];
            ldm4(ad, t4);
            bf[np * 2 + 0][0] = t4[0]; bf[np * 2 + 0][1] = t4[2];
            bf[np * 2 + 1][0] = t4[1]; bf[np * 2 + 1][1] = t4[3];
        }
        #pragma unroll
        for (int mt = 0; mt < 4; mt++)
            #pragma unroll
            for (int nt = 0; nt < 4; nt++)
                mma16816(acc[mt][nt], a[mt], bf[nt]);

        if (DO_EPI) epi_chunk<COL>(prev, kb, rowpart, colpart);
    }
}

__global__ void __launch_bounds__(NTHREADS, 1)
uniform_loss_main() {
    extern __shared__ char smem[];
    uint32_t sb = smem_u32(smem);
    float* rowsum = (float*)(smem + SM_ROW);

    const int tid  = threadIdx.x;
    const int lane = tid & 31;
    const int w    = tid >> 5;      // 0..7
    const int wm   = w & 1;         // 2 M-groups of 64 rows
    const int wn   = w >> 1;        // 4 N-groups of 32 cols
    const int rsel = lane & 15;
    const int csel = lane >> 4;
    const int g    = lane >> 2;

    const uint32_t sA = sb + SM_A;
    const uint32_t sB0 = sb + SM_B0;
    const uint32_t sB1 = sb + SM_B1;

    for (int it = blockIdx.x; it < ITEMS; it += gridDim.x) {
        // Decode item -> (i, chunk): row i covers j in [i, 96), chunked by 8.
        int t = it, i = 0;
        #pragma unroll 1
        for (; i < MTILES; i++) {
            int chunks = (MTILES - i + JC - 1) >> 3;
            if (t < chunks) break;
            t -= chunks;
        }
        const int j0 = i + t * JC;
        const int nj = min(JC, MTILES - j0);
        const bool diag0 = (j0 == i);    // tile 0 of this item is the diagonal block

        if (tid < 128) rowsum[tid] = 0.0f;

        // Prologue: A tile + B(j0) as group0; B(j0+1) as group1 (if present)
        issue_tile_load(sA,  g_xbf + (size_t)i  * 128 * DK, tid);
        issue_tile_load(sB0, g_xbf + (size_t)j0 * 128 * DK, tid);
        CP_COMMIT();
        if (nj > 1) {
            issue_tile_load(sB1, g_xbf + (size_t)(j0 + 1) * 128 * DK, tid);
            CP_COMMIT();
        }

        float rowpart[8], colpart[8];
        #pragma unroll
        for (int r = 0; r < 8; r++) { rowpart[r] = 0.0f; colpart[r] = 0.0f; }

        float accA[4][4][4];
        float accB[4][4][4];

        int jj = 0;
        bool lastA;
        #pragma unroll 1
        for (;;) {
            // ---- even slot: tile jj -> accA (buffer sB0); epi of accB ----
            if (jj == nj - 1) { CP_WAIT0(); } else { CP_WAIT1(); }
            __syncthreads();
            if (jj == 0)
                tile_step<false, false>(sA, sB0, accA, accB, rowpart, colpart,
                                        wm, wn, rsel, csel);
            else
                tile_step<true, true>(sA, sB0, accA, accB, rowpart, colpart,
                                      wm, wn, rsel, csel);
            __syncthreads();
            if (jj + 2 < nj) {
                issue_tile_load(sB0, g_xbf + (size_t)(j0 + jj + 2) * 128 * DK, tid);
                CP_COMMIT();
            }
            if (jj >= 1) col_flush(colpart, j0 + jj - 1, wn, lane);
            if (++jj == nj) { lastA = true; break; }

            // ---- odd slot: tile jj -> accB (buffer sB1); epi of accA ----
            if (jj == nj - 1) { CP_WAIT0(); } else { CP_WAIT1(); }
            __syncthreads();
            if (jj == 1 && diag0)
                tile_step<true, false>(sA, sB1, accB, accA, rowpart, colpart,
                                       wm, wn, rsel, csel);
            else
                tile_step<true, true>(sA, sB1, accB, accA, rowpart, colpart,
                                      wm, wn, rsel, csel);
            __syncthreads();
            if (jj + 2 < nj) {
                issue_tile_load(sB1, g_xbf + (size_t)(j0 + jj + 2) * 128 * DK, tid);
                CP_COMMIT();
            }
            if (!(jj == 1 && diag0)) col_flush(colpart, j0 + jj - 1, wn, lane);
            if (++jj == nj) { lastA = false; break; }
        }

        // Final epilogue: last tile (index nj-1)
        {
            const bool lastDiag = (nj == 1) && diag0;
            if (lastA) {
                if (lastDiag) {
                    #pragma unroll
                    for (int kb = 0; kb < 8; kb++)
                        epi_chunk<false>(accA, kb, rowpart, colpart);
                } else {
                    #pragma unroll
                    for (int kb = 0; kb < 8; kb++)
                        epi_chunk<true>(accA, kb, rowpart, colpart);
                }
            } else {
                #pragma unroll
                for (int kb = 0; kb < 8; kb++)
                    epi_chunk<true>(accB, kb, rowpart, colpart);
            }
            if (!lastDiag) col_flush(colpart, j0 + nj - 1, wn, lane);
        }

        // Reduce row partials: quad shuffle, SMEM atomics, then global add.
        #pragma unroll
        for (int r = 0; r < 8; r++) {
            float v = rowpart[r];
            v += __shfl_xor_sync(0xffffffffu, v, 1);
            v += __shfl_xor_sync(0xffffffffu, v, 2);
            if ((lane & 3) == 0) {
                int row = wm * 64 + (r >> 1) * 16 + (r & 1) * 8 + g;
                atomicAdd(&rowsum[row], v);
            }
        }
        __syncthreads();
        if (tid < 128)
            atomicAdd(&g_rowsum[i * 128 + tid], rowsum[tid]);
        __syncthreads();
    }
}

__global__ void finalize_kernel(float* __restrict__ out) {
    int i = blockIdx.x * blockDim.x + threadIdx.x;   // 0..NROWS-1
    float L = __logf(g_rowsum[i]);

    #pragma unroll
    for (int o = 16; o > 0; o >>= 1) L += __shfl_xor_sync(0xffffffffu, L, o);

    __shared__ float ws[8];
    int lane = threadIdx.x & 31, wid = threadIdx.x >> 5;
    if (lane == 0) ws[wid] = L;
    __syncthreads();
    if (threadIdx.x == 0) {
        float t = 0.0f;
        #pragma unroll
        for (int k = 0; k < 8; k++) t += ws[k];
        atomicAdd(out, t * (1.0f / (float)NROWS));
    }
}

// ---------------- host launch ----------------

extern "C" void kernel_launch(void* const* d_in, const int* in_sizes, int n_in,
                              void* d_out, int out_size) {
    const float* x = (const float*)d_in[0];
    float* out = (float*)d_out;

    int nconv = NROWS * DK / 4;
    convert_kernel<<<(nconv + 255) / 256, 256>>>(x, out);

    cudaFuncSetAttribute(uniform_loss_main,
                         cudaFuncAttributeMaxDynamicSharedMemorySize, SM_TOTAL);
    uniform_loss_main<<<GRID, NTHREADS, SM_TOTAL>>>();

    finalize_kernel<<<NROWS / 256, 256>>>(out);
}

// round 8
// speedup vs baseline: 1.4465x; 1.1118x over previous
#include <cuda_runtime.h>
#include <cuda_bf16.h>
#include <cstdint>

// Problem constants
#define NROWS   12288
#define DK      128
#define MTILES  96           // NROWS / 128
#define JC      8            // j-tiles per work item (chunk)
#define ITEMS   624          // sum_i ceil((96-i)/8)
#define GRID    148
#define NTHREADS 256

// SMEM layout (dynamic): A tile 32KB, B double buffer 2x32KB
#define SM_A     0
#define SM_B0    32768
#define SM_B1    65536
#define SM_TOTAL 98304

// exp(sim/T) = 2^(dot * log2(e)/T)
static constexpr float EXP_SCALE = 1.4426950408889634f / 0.07f;

// Scratch (allocation-free)
__device__ __nv_bfloat16 g_xbf[NROWS * DK];
__device__ float g_rowsum[NROWS];
__device__ int   g_ticket;

// ---------------- PTX helpers (base sm_103 target only) ----------------
__device__ __forceinline__ uint32_t smem_u32(const void* p) {
    uint32_t a;
    asm("{ .reg .u64 t; cvta.to.shared.u64 t, %1; cvt.u32.u64 %0, t; }" : "=r"(a) : "l"(p));
    return a;
}

__device__ __forceinline__ void cp16(uint32_t dst, const void* src) {
    asm volatile("cp.async.cg.shared.global [%0], [%1], 16;" :: "r"(dst), "l"(src));
}
#define CP_COMMIT() asm volatile("cp.async.commit_group;" ::: "memory")
#define CP_WAIT1()  asm volatile("cp.async.wait_group 1;" ::: "memory")
#define CP_WAIT0()  asm volatile("cp.async.wait_group 0;" ::: "memory")

__device__ __forceinline__ void ldm4(uint32_t addr, uint32_t* r) {
    asm volatile("ldmatrix.sync.aligned.m8n8.x4.shared.b16 {%0,%1,%2,%3}, [%4];"
        : "=r"(r[0]), "=r"(r[1]), "=r"(r[2]), "=r"(r[3]) : "r"(addr));
}

__device__ __forceinline__ void mma16816(float* c, const uint32_t* a, const uint32_t* b) {
    asm volatile(
        "mma.sync.aligned.m16n8k16.row.col.f32.bf16.bf16.f32 "
        "{%0,%1,%2,%3}, {%4,%5,%6,%7}, {%8,%9}, {%0,%1,%2,%3};"
        : "+f"(c[0]), "+f"(c[1]), "+f"(c[2]), "+f"(c[3])
        : "r"(a[0]), "r"(a[1]), "r"(a[2]), "r"(a[3]), "r"(b[0]), "r"(b[1]));
}

__device__ __forceinline__ float fast_exp2(float x) {
    float r;
    asm("ex2.approx.f32 %0, %1;" : "=f"(r) : "f"(x));
    return r;
}

// ---------------- kernels ----------------

__global__ void convert_kernel(const float* __restrict__ x, float* __restrict__ out) {
    int i = blockIdx.x * blockDim.x + threadIdx.x;
    if (i < NROWS * DK / 4) {
        float4 v = reinterpret_cast<const float4*>(x)[i];
        __nv_bfloat162* dst = reinterpret_cast<__nv_bfloat162*>(g_xbf);
        dst[2 * i]     = __floats2bfloat162_rn(v.x, v.y);
        dst[2 * i + 1] = __floats2bfloat162_rn(v.z, v.w);
    }
    if (i < NROWS) g_rowsum[i] = 0.0f;   // reset every launch (graph replay)
    if (i == 0) { out[0] = 0.0f; g_ticket = GRID; }
}

// Load one 128x128 bf16 tile (row-major 256B rows) into SMEM with XOR-16B swizzle.
__device__ __forceinline__ void issue_tile_load(uint32_t sdst, const __nv_bfloat16* gsrc,
                                                int tid) {
    const char* base = (const char*)gsrc;
    #pragma unroll
    for (int t = 0; t < 8; t++) {
        int q   = tid + t * NTHREADS;      // 0..2047
        int row = q >> 4;
        int col = q & 15;
        cp16(sdst + row * 256 + ((col ^ (row & 7)) << 4),
             base + row * 256 + col * 16);
    }
}

// Pure MMA for one 128x128 tile into acc.
__device__ __forceinline__ void tile_mma(uint32_t sA, uint32_t bufb,
                                         float (&acc)[4][4][4],
                                         int wm, int wn, int rsel, int csel) {
    #pragma unroll
    for (int mt = 0; mt < 4; mt++)
        #pragma unroll
        for (int nt = 0; nt < 4; nt++)
            #pragma unroll
            for (int ci = 0; ci < 4; ci++) acc[mt][nt][ci] = 0.0f;

    #pragma unroll
    for (int kb = 0; kb < 8; kb++) {
        uint32_t a[4][4];
        #pragma unroll
        for (int mt = 0; mt < 4; mt++) {
            int row = wm * 64 + mt * 16 + rsel;
            uint32_t ad = sA + row * 256 + (((kb * 2 + csel) ^ (row & 7)) << 4);
            ldm4(ad, a[mt]);
        }
        uint32_t bf[4][2];
        #pragma unroll
        for (int np = 0; np < 2; np++) {
            int row = wn * 32 + np * 16 + rsel;
            uint32_t ad = bufb + row * 256 + (((kb * 2 + csel) ^ (row & 7)) << 4);
            uint32_t t4[4];
            ldm4(ad, t4);
            bf[np * 2 + 0][0] = t4[0]; bf[np * 2 + 0][1] = t4[2];
            bf[np * 2 + 1][0] = t4[1]; bf[np * 2 + 1][1] = t4[3];
        }
        #pragma unroll
        for (int mt = 0; mt < 4; mt++)
            #pragma unroll
            for (int nt = 0; nt < 4; nt++)
                mma16816(acc[mt][nt], a[mt], bf[nt]);
    }
}

// Full-tile epilogue: exp into rowpart (+ colpart when off-diag).
template <bool COL>
__device__ __forceinline__ void tile_epi(const float (&acc)[4][4][4],
                                         float (&rowpart)[8], float (&colpart)[8]) {
    #pragma unroll
    for (int mt = 0; mt < 4; mt++)
        #pragma unroll
        for (int nt = 0; nt < 4; nt++) {
            float e0 = fast_exp2(acc[mt][nt][0] * EXP_SCALE);
            float e1 = fast_exp2(acc[mt][nt][1] * EXP_SCALE);
            float e2 = fast_exp2(acc[mt][nt][2] * EXP_SCALE);
            float e3 = fast_exp2(acc[mt][nt][3] * EXP_SCALE);
            rowpart[mt * 2 + 0] += e0 + e1;
            rowpart[mt * 2 + 1] += e2 + e3;
            if (COL) {
                colpart[nt * 2 + 0] += e0 + e2;
                colpart[nt * 2 + 1] += e1 + e3;
            }
        }
}

// Flush column partials of one completed off-diag tile to g_rowsum[jglob block].
__device__ __forceinline__ void col_flush(float (&colpart)[8], int jglob,
                                          int wn, int lane) {
    #pragma unroll
    for (int q = 0; q < 8; q++) {
        float v = colpart[q];
        v += __shfl_xor_sync(0xffffffffu, v, 4);
        v += __shfl_xor_sync(0xffffffffu, v, 8);
        v += __shfl_xor_sync(0xffffffffu, v, 16);
        if (lane < 4) {
            int col = jglob * 128 + wn * 32 + (q >> 1) * 8 + lane * 2 + (q & 1);
            atomicAdd(&g_rowsum[col], v);
        }
        colpart[q] = 0.0f;
    }
}

__global__ void __launch_bounds__(NTHREADS, 1)
uniform_loss_main() {
    extern __shared__ char smem[];
    uint32_t sb = smem_u32(smem);
    __shared__ int s_item;

    const int tid  = threadIdx.x;
    const int lane = tid & 31;
    const int w    = tid >> 5;      // 0..7
    const int wm   = w & 1;         // 2 M-groups of 64 rows
    const int wn   = w >> 1;        // 4 N-groups of 32 cols
    const int rsel = lane & 15;
    const int csel = lane >> 4;
    const int g    = lane >> 2;

    const uint32_t sA = sb + SM_A;
    const uint32_t sBuf[2] = { sb + SM_B0, sb + SM_B1 };

    int it = blockIdx.x;            // first item: static; rest via ticket
    #pragma unroll 1
    while (it < ITEMS) {
        // Decode item -> (i, chunk): row i covers j in [i, 96), chunked by 8.
        int t = it, i = 0;
        #pragma unroll 1
        for (; i < MTILES; i++) {
            int chunks = (MTILES - i + JC - 1) >> 3;
            if (t < chunks) break;
            t -= chunks;
        }
        const int j0 = i + t * JC;
        const int nj = min(JC, MTILES - j0);
        const bool diag0 = (j0 == i);

        // Prologue: A tile + B(j0) as group0; B(j0+1) as group1 (if present)
        issue_tile_load(sA,      g_xbf + (size_t)i  * 128 * DK, tid);
        issue_tile_load(sBuf[0], g_xbf + (size_t)j0 * 128 * DK, tid);
        CP_COMMIT();
        if (nj > 1) {
            issue_tile_load(sBuf[1], g_xbf + (size_t)(j0 + 1) * 128 * DK, tid);
            CP_COMMIT();
        }

        float rowpart[8], colpart[8];
        #pragma unroll
        for (int r = 0; r < 8; r++) { rowpart[r] = 0.0f; colpart[r] = 0.0f; }

        float acc[4][4][4];

        #pragma unroll 1
        for (int jj = 0; jj < nj; jj++) {
            if (jj == nj - 1) { CP_WAIT0(); } else { CP_WAIT1(); }
            __syncthreads();
            tile_mma(sA, sBuf[jj & 1], acc, wm, wn, rsel, csel);
            __syncthreads();
            if (jj + 2 < nj) {
                issue_tile_load(sBuf[jj & 1],
                                g_xbf + (size_t)(j0 + jj + 2) * 128 * DK, tid);
                CP_COMMIT();
            }
            // Epilogue overlaps the cp.async just issued.
            if (jj == 0 && diag0) {
                tile_epi<false>(acc, rowpart, colpart);
            } else {
                tile_epi<true>(acc, rowpart, colpart);
                col_flush(colpart, j0 + jj, wn, lane);
            }
        }

        // Flush row partials: quad shuffle then direct global atomics.
        #pragma unroll
        for (int r = 0; r < 8; r++) {
            float v = rowpart[r];
            v += __shfl_xor_sync(0xffffffffu, v, 1);
            v += __shfl_xor_sync(0xffffffffu, v, 2);
            if ((lane & 3) == 0) {
                int row = i * 128 + wm * 64 + (r >> 1) * 16 + (r & 1) * 8 + g;
                atomicAdd(&g_rowsum[row], v);
            }
        }

        // Grab next item (dynamic balance).
        __syncthreads();
        if (tid == 0) s_item = atomicAdd(&g_ticket, 1);
        __syncthreads();
        it = s_item;
    }
}

__global__ void finalize_kernel(float* __restrict__ out) {
    int i = blockIdx.x * blockDim.x + threadIdx.x;   // 0..NROWS-1
    float L = __logf(g_rowsum[i]);

    #pragma unroll
    for (int o = 16; o > 0; o >>= 1) L += __shfl_xor_sync(0xffffffffu, L, o);

    __shared__ float ws[8];
    int lane = threadIdx.x & 31, wid = threadIdx.x >> 5;
    if (lane == 0) ws[wid] = L;
    __syncthreads();
    if (threadIdx.x == 0) {
        float t = 0.0f;
        #pragma unroll
        for (int k = 0; k < 8; k++) t += ws[k];
        atomicAdd(out, t * (1.0f / (float)NROWS));
    }
}

// ---------------- host launch ----------------

extern "C" void kernel_launch(void* const* d_in, const int* in_sizes, int n_in,
                              void* d_out, int out_size) {
    const float* x = (const float*)d_in[0];
    float* out = (float*)d_out;

    int nconv = NROWS * DK / 4;
    convert_kernel<<<(nconv + 255) / 256, 256>>>(x, out);

    cudaFuncSetAttribute(uniform_loss_main,
                         cudaFuncAttributeMaxDynamicSharedMemorySize, SM_TOTAL);
    uniform_loss_main<<<GRID, NTHREADS, SM_TOTAL>>>();

    finalize_kernel<<<NROWS / 256, 256>>>(out);
}